// round 2
// baseline (speedup 1.0000x reference)
#include <cuda_runtime.h>
#include <math.h>

#define SEQ   256
#define NB    32
#define REC   16
#define EMB   32
#define VOCAB 32000
#define ROWS  (SEQ*NB)        /* 8192 */

/* vocab-pass config: 256 threads x 4 cols = 1024 cols/block, 32 rows/block */
#define VP_THREADS 256
#define VP_COLS    1024
#define VP_NCH     32          /* 32*1024 = 32768 >= 32000 */
#define VP_ROWS    32
#define VP_ROWT    (ROWS/VP_ROWS)   /* 256 */

__device__ float g_ih[ROWS*REC];
__device__ float g_hidden[ROWS*REC];
__device__ float g_part[ROWS*VP_NCH];
__device__ float g_lse[ROWS];

/* ---- f32x2 packed helpers (sm_103a FFMA2 path, PTX-only) ---- */
__device__ __forceinline__ unsigned long long pack2(float lo, float hi) {
    unsigned long long r;
    asm("mov.b64 %0, {%1, %2};" : "=l"(r) : "f"(lo), "f"(hi));
    return r;
}
__device__ __forceinline__ void unpack2(unsigned long long v, float& lo, float& hi) {
    asm("mov.b64 {%0, %1}, %2;" : "=f"(lo), "=f"(hi) : "l"(v));
}
__device__ __forceinline__ unsigned long long fma2(unsigned long long a,
                                                   unsigned long long b,
                                                   unsigned long long c) {
    unsigned long long d;
    asm("fma.rn.f32x2 %0, %1, %2, %3;" : "=l"(d) : "l"(a), "l"(b), "l"(c));
    return d;
}
__device__ __forceinline__ unsigned long long add2(unsigned long long a,
                                                   unsigned long long b) {
    unsigned long long d;
    asm("add.rn.f32x2 %0, %1, %2;" : "=l"(d) : "l"(a), "l"(b));
    return d;
}

/* ---------------- kernel 1: i_h = emb[idx] @ U^T + b1 ---------------- */
__global__ void k_ih(const int* __restrict__ inp, const float* __restrict__ emb,
                     const float* __restrict__ U, const float* __restrict__ b1)
{
    int gid = blockIdx.x*blockDim.x + threadIdx.x;
    if (gid >= ROWS*REC) return;
    int row = gid >> 4;
    int r   = gid & 15;
    int idx = inp[row];
    const float4* e4 = (const float4*)(emb + (size_t)idx*EMB);
    const float4* u4 = (const float4*)(U + r*EMB);
    float acc = b1[r];
    #pragma unroll
    for (int q = 0; q < 8; q++) {
        float4 e = e4[q], u = u4[q];
        acc += e.x*u.x + e.y*u.y + e.z*u.z + e.w*u.w;
    }
    g_ih[gid] = acc;
}

/* ---------------- kernel 2: sequential recurrence (1 warp / batch) ----
   g_ih for this batch staged in shared so the 256-step serial chain never
   waits on DRAM. hidden[s] stores h BEFORE the update (matches scan).    */
__global__ void k_rnn(const float* __restrict__ W, const float* __restrict__ b2,
                      const float* __restrict__ h0)
{
    int b = blockIdx.x;
    int r = threadIdx.x;
    __shared__ __align__(16) float ihs[SEQ*REC];   /* 16 KB */
    __shared__ float hs[REC];

    for (int s = r; s < SEQ; s += 32) {
        const float4* src = (const float4*)(g_ih + (size_t)(s*NB + b)*REC);
        float4* dst = (float4*)(ihs + s*REC);
        dst[0] = src[0]; dst[1] = src[1]; dst[2] = src[2]; dst[3] = src[3];
    }
    float wrow[REC];
    float bias = 0.f;
    if (r < REC) {
        hs[r] = h0[r];
        #pragma unroll
        for (int k = 0; k < REC; k++) wrow[k] = W[r*REC + k];
        bias = b2[r];
    }
    __syncwarp();
    for (int s = 0; s < SEQ; s++) {
        float hn = 0.f;
        if (r < REC) {
            int row = s*NB + b;
            g_hidden[row*REC + r] = hs[r];          /* pre-update h */
            float acc = ihs[s*REC + r] + bias;
            #pragma unroll
            for (int k = 0; k < REC; k++) acc += wrow[k]*hs[k];
            hn = tanhf(acc);
        }
        __syncwarp();
        if (r < REC) hs[r] = hn;
        __syncwarp();
    }
}

/* ---------------- kernel 3: per-row sum of exp over 1024-col chunk.
   V (4 cols/thread) packed in regs; h duplicated (h,h) in shared ->
   8 LDS.128 + 32 FFMA2 per row. Warp-shuffle reduce per row.             */
__global__ void k_sumexp(const float* __restrict__ V)
{
    __shared__ __align__(16) unsigned long long hs2[VP_ROWS*REC];  /* 4 KB */
    __shared__ float red8[VP_ROWS*8];                              /* 1 KB */
    int tid = threadIdx.x, wid = tid >> 5, lid = tid & 31;
    int rowBase = blockIdx.y * VP_ROWS;
    int c0 = blockIdx.x * VP_COLS + tid*4;

    for (int i = tid; i < VP_ROWS*REC; i += VP_THREADS) {
        float h = g_hidden[(size_t)(rowBase + (i >> 4))*REC + (i & 15)];
        hs2[i] = pack2(h, h);
    }
    __syncthreads();

    bool valid = (c0 < VOCAB);
    unsigned long long v01[REC], v23[REC];
    if (valid) {
        const float4* p = (const float4*)(V + (size_t)c0*REC);
        #pragma unroll
        for (int q = 0; q < 4; q++) {
            float4 a = p[q], b = p[4+q], c = p[8+q], d = p[12+q];
            v01[q*4+0] = pack2(a.x, b.x); v01[q*4+1] = pack2(a.y, b.y);
            v01[q*4+2] = pack2(a.z, b.z); v01[q*4+3] = pack2(a.w, b.w);
            v23[q*4+0] = pack2(c.x, d.x); v23[q*4+1] = pack2(c.y, d.y);
            v23[q*4+2] = pack2(c.z, d.z); v23[q*4+3] = pack2(c.w, d.w);
        }
    } else {
        #pragma unroll
        for (int k = 0; k < REC; k++) { v01[k] = 0ull; v23[k] = 0ull; }
    }

    #pragma unroll 4
    for (int rr = 0; rr < VP_ROWS; rr++) {
        const ulonglong2* hp2 = (const ulonglong2*)(hs2 + rr*REC);
        unsigned long long acc01 = 0ull, acc23 = 0ull;
        #pragma unroll
        for (int q = 0; q < 8; q++) {
            ulonglong2 hh = hp2[q];
            acc01 = fma2(hh.x, v01[2*q],   acc01);
            acc23 = fma2(hh.x, v23[2*q],   acc23);
            acc01 = fma2(hh.y, v01[2*q+1], acc01);
            acc23 = fma2(hh.y, v23[2*q+1], acc23);
        }
        float e0, e1, e2, e3;
        unpack2(acc01, e0, e1);
        unpack2(acc23, e2, e3);
        float s = valid ? (__expf(e0) + __expf(e1)) + (__expf(e2) + __expf(e3))
                        : 0.f;
        #pragma unroll
        for (int off = 16; off; off >>= 1)
            s += __shfl_xor_sync(0xffffffffu, s, off);
        if (lid == 0) red8[rr*8 + wid] = s;
    }
    __syncthreads();
    if (tid < VP_ROWS) {
        float t = 0.f;
        #pragma unroll
        for (int j = 0; j < 8; j++) t += red8[tid*8 + j];
        g_part[(size_t)(rowBase + tid)*VP_NCH + blockIdx.x] = t;
    }
}

/* ---------------- kernel 4: lse[row] = log(sum of partials) ---------- */
__global__ void k_lse()
{
    int row = blockIdx.x*blockDim.x + threadIdx.x;
    if (row >= ROWS) return;
    float s = 0.f;
    #pragma unroll
    for (int i = 0; i < VP_NCH; i++) s += g_part[(size_t)row*VP_NCH + i];
    g_lse[row] = logf(s);
}

/* ---------------- kernel 5: out = logit - lse (recompute GEMM) --------
   Same packed structure as k_sumexp; epilogue is add of (-lse,-lse)
   and one STG.128 per row per thread.                                   */
__global__ void k_write(const float* __restrict__ V, float* __restrict__ out)
{
    __shared__ __align__(16) unsigned long long hs2[VP_ROWS*REC];
    __shared__ unsigned long long nl2[VP_ROWS];
    int tid = threadIdx.x;
    int rowBase = blockIdx.y * VP_ROWS;
    int c0 = blockIdx.x * VP_COLS + tid*4;

    for (int i = tid; i < VP_ROWS*REC; i += VP_THREADS) {
        float h = g_hidden[(size_t)(rowBase + (i >> 4))*REC + (i & 15)];
        hs2[i] = pack2(h, h);
    }
    if (tid < VP_ROWS) {
        float l = g_lse[rowBase + tid];
        nl2[tid] = pack2(-l, -l);
    }
    __syncthreads();

    if (c0 >= VOCAB) return;

    unsigned long long v01[REC], v23[REC];
    {
        const float4* p = (const float4*)(V + (size_t)c0*REC);
        #pragma unroll
        for (int q = 0; q < 4; q++) {
            float4 a = p[q], b = p[4+q], c = p[8+q], d = p[12+q];
            v01[q*4+0] = pack2(a.x, b.x); v01[q*4+1] = pack2(a.y, b.y);
            v01[q*4+2] = pack2(a.z, b.z); v01[q*4+3] = pack2(a.w, b.w);
            v23[q*4+0] = pack2(c.x, d.x); v23[q*4+1] = pack2(c.y, d.y);
            v23[q*4+2] = pack2(c.z, d.z); v23[q*4+3] = pack2(c.w, d.w);
        }
    }

    #pragma unroll 4
    for (int rr = 0; rr < VP_ROWS; rr++) {
        const ulonglong2* hp2 = (const ulonglong2*)(hs2 + rr*REC);
        unsigned long long acc01 = 0ull, acc23 = 0ull;
        #pragma unroll
        for (int q = 0; q < 8; q++) {
            ulonglong2 hh = hp2[q];
            acc01 = fma2(hh.x, v01[2*q],   acc01);
            acc23 = fma2(hh.x, v23[2*q],   acc23);
            acc01 = fma2(hh.y, v01[2*q+1], acc01);
            acc23 = fma2(hh.y, v23[2*q+1], acc23);
        }
        unsigned long long nl = nl2[rr];
        ulonglong2 st;
        st.x = add2(acc01, nl);
        st.y = add2(acc23, nl);
        *(ulonglong2*)(out + (size_t)(rowBase + rr)*VOCAB + c0) = st;
    }
}

extern "C" void kernel_launch(void* const* d_in, const int* in_sizes, int n_in,
                              void* d_out, int out_size)
{
    const int*   inp = (const int*)d_in[0];
    const float* emb = (const float*)d_in[1];
    const float* U   = (const float*)d_in[2];
    const float* W   = (const float*)d_in[3];
    const float* V   = (const float*)d_in[4];
    const float* b1  = (const float*)d_in[5];
    const float* b2  = (const float*)d_in[6];
    const float* h0  = (const float*)d_in[7];
    float* out = (float*)d_out;

    k_ih<<<(ROWS*REC + 255)/256, 256>>>(inp, emb, U, b1);
    k_rnn<<<NB, 32>>>(W, b2, h0);
    k_sumexp<<<dim3(VP_NCH, VP_ROWT), VP_THREADS>>>(V);
    k_lse<<<(ROWS + 255)/256, 256>>>();
    k_write<<<dim3(VP_NCH, VP_ROWT), VP_THREADS>>>(V, out);
}

// round 5
// speedup vs baseline: 1.4897x; 1.4897x over previous
#include <cuda_runtime.h>
#include <math.h>
#include <stdint.h>

#define SEQ   256
#define NB    32
#define REC   16
#define EMB   32
#define VOCAB 32000
#define ROWS  (SEQ*NB)        /* 8192 */

#define BLK_M   64
#define BLK_N   512
#define NBLK_N  63                 /* ceil(32000/512) */
#define NBLK_M  (ROWS/BLK_M)       /* 128 */
#define NPART   (NBLK_N*4)         /* 252 partials per row (n-groups of 128) */
#define VTHREADS 512
#define VS_STRIDE 520              /* padded n-stride: 520%32==8 -> conflict-free frags */

__device__ float g_ih[ROWS*REC];
__device__ float g_hidden[ROWS*REC];
__device__ float g_part[ROWS*NPART];
__device__ float g_lse[ROWS];

/* ---- tf32 mma helpers ---- */
__device__ __forceinline__ uint32_t f2tf32(float x) {
    uint32_t r; asm("cvt.rna.tf32.f32 %0, %1;" : "=r"(r) : "f"(x)); return r;
}
__device__ __forceinline__ void mma_tf32(float* d, const uint32_t* a,
                                         uint32_t b0, uint32_t b1) {
    asm volatile(
        "mma.sync.aligned.m16n8k8.row.col.f32.tf32.tf32.f32 "
        "{%0,%1,%2,%3}, {%4,%5,%6,%7}, {%8,%9}, {%0,%1,%2,%3};\n"
        : "+f"(d[0]), "+f"(d[1]), "+f"(d[2]), "+f"(d[3])
        : "r"(a[0]), "r"(a[1]), "r"(a[2]), "r"(a[3]), "r"(b0), "r"(b1));
}

/* ---------------- kernel 1: i_h = emb[idx] @ U^T + b1 ---------------- */
__global__ void k_ih(const int* __restrict__ inp, const float* __restrict__ emb,
                     const float* __restrict__ U, const float* __restrict__ b1)
{
    int gid = blockIdx.x*blockDim.x + threadIdx.x;
    if (gid >= ROWS*REC) return;
    int row = gid >> 4;
    int r   = gid & 15;
    int idx = inp[row];
    const float4* e4 = (const float4*)(emb + (size_t)idx*EMB);
    const float4* u4 = (const float4*)(U + r*EMB);
    float acc = b1[r];
    #pragma unroll
    for (int q = 0; q < 8; q++) {
        float4 e = e4[q], u = u4[q];
        acc += e.x*u.x + e.y*u.y + e.z*u.z + e.w*u.w;
    }
    g_ih[gid] = acc;
}

/* ---------------- kernel 2: sequential recurrence (1 warp / batch) ---- */
__global__ void k_rnn(const float* __restrict__ W, const float* __restrict__ b2,
                      const float* __restrict__ h0)
{
    int b = blockIdx.x;
    int r = threadIdx.x;
    __shared__ __align__(16) float ihs[SEQ*REC];   /* 16 KB */
    __shared__ float hs[REC];

    for (int s = r; s < SEQ; s += 32) {
        const float4* src = (const float4*)(g_ih + (size_t)(s*NB + b)*REC);
        float4* dst = (float4*)(ihs + s*REC);
        dst[0] = src[0]; dst[1] = src[1]; dst[2] = src[2]; dst[3] = src[3];
    }
    float wrow[REC];
    float bias = 0.f;
    if (r < REC) {
        hs[r] = h0[r];
        #pragma unroll
        for (int k = 0; k < REC; k++) wrow[k] = W[r*REC + k];
        bias = b2[r];
    }
    __syncwarp();
    for (int s = 0; s < SEQ; s++) {
        float hn = 0.f;
        if (r < REC) {
            int row = s*NB + b;
            g_hidden[row*REC + r] = hs[r];          /* pre-update h */
            float acc = ihs[s*REC + r] + bias;
            #pragma unroll
            for (int k = 0; k < REC; k++) acc += wrow[k]*hs[k];
            hn = tanhf(acc);
        }
        __syncwarp();
        if (r < REC) hs[r] = hn;
        __syncwarp();
    }
}

/* ---------------- vocab GEMM via tf32 mma.sync -----------------------
   WRITE=0: per-row sum of exp(logit) partials.   WRITE=1: out = logit - lse.
   Block: 512 thr / 16 warps. Tile M=64 x N=512.
   warp w: m-group mg = w&3 (16 rows), n-group ng = w>>2 (128 cols).
   V^T staged in shared as tf32, Vs[k][n], stride 520 (conflict-free).     */
template<int WRITE>
__global__ void __launch_bounds__(VTHREADS, 1)
k_vocab(const float* __restrict__ V, float* __restrict__ out)
{
    __shared__ __align__(16) uint32_t Vs[REC*VS_STRIDE];   /* 33.3 KB */
    int tid  = threadIdx.x;
    int lane = tid & 31;
    int w    = tid >> 5;
    int mg   = w & 3;
    int ng   = w >> 2;
    int rowBase = blockIdx.y * BLK_M;
    int nBase   = blockIdx.x * BLK_N;

    /* stage V^T (tf32): thread n loads one V row, scatters 16 STS */
    {
        int n  = tid;
        int gn = nBase + n;
        float4 q0, q1, q2, q3;
        if (gn < VOCAB) {
            const float4* p = (const float4*)(V + (size_t)gn*REC);
            q0 = p[0]; q1 = p[1]; q2 = p[2]; q3 = p[3];
        } else {
            q0 = q1 = q2 = q3 = make_float4(0.f,0.f,0.f,0.f);
        }
        float vv[REC] = {q0.x,q0.y,q0.z,q0.w, q1.x,q1.y,q1.z,q1.w,
                         q2.x,q2.y,q2.z,q2.w, q3.x,q3.y,q3.z,q3.w};
        #pragma unroll
        for (int k = 0; k < REC; k++)
            Vs[k*VS_STRIDE + n] = f2tf32(vv[k]);
    }

    /* A fragments: rows rowBase+mg*16+g and +8, K=16 in 2 halves */
    int g = lane >> 2, c = lane & 3;
    int r0i = rowBase + mg*16 + g;
    int r1i = r0i + 8;
    uint32_t a[2][4];
    #pragma unroll
    for (int kh = 0; kh < 2; kh++) {
        a[kh][0] = f2tf32(g_hidden[(size_t)r0i*REC + kh*8 + c]);
        a[kh][1] = f2tf32(g_hidden[(size_t)r1i*REC + kh*8 + c]);
        a[kh][2] = f2tf32(g_hidden[(size_t)r0i*REC + kh*8 + c + 4]);
        a[kh][3] = f2tf32(g_hidden[(size_t)r1i*REC + kh*8 + c + 4]);
    }
    float lse0 = 0.f, lse1 = 0.f;
    if (WRITE) { lse0 = g_lse[r0i]; lse1 = g_lse[r1i]; }
    __syncthreads();

    float sum0 = 0.f, sum1 = 0.f;
    int nCol0 = nBase + ng*128;

    #pragma unroll
    for (int t = 0; t < 16; t++) {
        int nc = ng*128 + t*8;            /* n offset inside shared tile */
        float d[4] = {0.f, 0.f, 0.f, 0.f};
        #pragma unroll
        for (int kh = 0; kh < 2; kh++) {
            uint32_t b0 = Vs[(kh*8 + c    )*VS_STRIDE + nc + g];
            uint32_t b1 = Vs[(kh*8 + c + 4)*VS_STRIDE + nc + g];
            mma_tf32(d, a[kh], b0, b1);
        }
        int gcol = nCol0 + t*8 + 2*c;     /* tile-aligned validity: gcol<VOCAB
                                             implies gcol+1<VOCAB (VOCAB%8==0) */
        if (WRITE) {
            if (gcol < VOCAB) {
                *(float2*)(out + (size_t)r0i*VOCAB + gcol) =
                    make_float2(d[0]-lse0, d[1]-lse0);
                *(float2*)(out + (size_t)r1i*VOCAB + gcol) =
                    make_float2(d[2]-lse1, d[3]-lse1);
            }
        } else {
            if (gcol < VOCAB) {
                sum0 += __expf(d[0]) + __expf(d[1]);
                sum1 += __expf(d[2]) + __expf(d[3]);
            }
        }
    }

    if (!WRITE) {
        /* reduce across the 4 lanes sharing the same row-group g */
        sum0 += __shfl_xor_sync(0xffffffffu, sum0, 1);
        sum0 += __shfl_xor_sync(0xffffffffu, sum0, 2);
        sum1 += __shfl_xor_sync(0xffffffffu, sum1, 1);
        sum1 += __shfl_xor_sync(0xffffffffu, sum1, 2);
        if (c == 0) {
            int pi = blockIdx.x*4 + ng;
            g_part[(size_t)r0i*NPART + pi] = sum0;
            g_part[(size_t)r1i*NPART + pi] = sum1;
        }
    }
}

/* ---------------- lse[row] = log(sum of 252 partials) ---------------- */
__global__ void k_lse()
{
    int row = blockIdx.x*blockDim.x + threadIdx.x;
    if (row >= ROWS) return;
    const float4* p = (const float4*)(g_part + (size_t)row*NPART);
    float s = 0.f;
    #pragma unroll
    for (int i = 0; i < NPART/4; i++) {
        float4 v = p[i];
        s += (v.x + v.y) + (v.z + v.w);
    }
    g_lse[row] = logf(s);
}

extern "C" void kernel_launch(void* const* d_in, const int* in_sizes, int n_in,
                              void* d_out, int out_size)
{
    const int*   inp = (const int*)d_in[0];
    const float* emb = (const float*)d_in[1];
    const float* U   = (const float*)d_in[2];
    const float* W   = (const float*)d_in[3];
    const float* V   = (const float*)d_in[4];
    const float* b1  = (const float*)d_in[5];
    const float* b2  = (const float*)d_in[6];
    const float* h0  = (const float*)d_in[7];
    float* out = (float*)d_out;

    k_ih<<<(ROWS*REC + 255)/256, 256>>>(inp, emb, U, b1);
    k_rnn<<<NB, 32>>>(W, b2, h0);
    k_vocab<0><<<dim3(NBLK_N, NBLK_M), VTHREADS>>>(V, nullptr);
    k_lse<<<(ROWS + 255)/256, 256>>>();
    k_vocab<1><<<dim3(NBLK_N, NBLK_M), VTHREADS>>>(V, out);
}